// round 16
// baseline (speedup 1.0000x reference)
#include <cuda_runtime.h>
#include <cuda_bf16.h>
#include <stdint.h>
#include <math.h>

#define BB 4
#define CC 256
#define HH 64
#define WW 64
#define NN (HH*WW)      // 4096
#define CQK 32

// ---- scratch (static device globals; no allocation) ----
__device__ __nv_bfloat16 g_Qhl[BB*NN*64];           // 2 MB   [b][n][hi d0..31 | lo d0..31]
__device__ __nv_bfloat16 g_Khl[BB*NN*64];           // 2 MB   [b][n][hi | lo]
__device__ __nv_bfloat16 g_Vbf[BB*CC*NN];           // 8 MB   [b][c][n]
__device__ __nv_bfloat16 g_P[(size_t)BB*NN*NN];     // 128 MB P=exp(S^T): [b][k][q]
__device__ float g_Lpart[BB*NN*2];                  // partial col sums (per k, q-half)
__device__ __nv_bfloat16 g_xT[(size_t)BB*NN*CC];    // 8 MB   xT: [b][n][ci]
__device__ __nv_bfloat16 g_WtV[9*CC*CC];            // 1.1 MB [t][co][ci]
__device__ __nv_bfloat16 g_WtQK[9*64*CC];           // 288 KB [t][co(q0-31,k32-63)][ci]

// ============================================================
// helpers
// ============================================================
__device__ __forceinline__ uint32_t smem_u32(const void* p) {
    uint32_t a;
    asm("{ .reg .u64 t; cvta.to.shared.u64 t, %1; cvt.u32.u64 %0, t; }"
        : "=r"(a) : "l"(p));
    return a;
}
#define SWZ(x) ((x) ^ (((x) >> 3) & 0x70))
#define STS128U(addr, a, b, c, d) \
    asm volatile("st.shared.v4.b32 [%0], {%1, %2, %3, %4};" \
                 :: "r"(addr), "r"(a), "r"(b), "r"(c), "r"(d) : "memory")
#define STS32U(addr, a) \
    asm volatile("st.shared.b32 [%0], %1;" :: "r"(addr), "r"(a) : "memory")
#define LDS128U(r0, r1, r2, r3, addr) \
    asm volatile("ld.shared.v4.b32 {%0,%1,%2,%3}, [%4];" \
                 : "=r"(r0), "=r"(r1), "=r"(r2), "=r"(r3) : "r"(addr))
#define LDMX4(r0, r1, r2, r3, a) \
    asm volatile("ldmatrix.sync.aligned.m8n8.x4.shared.b16 {%0,%1,%2,%3}, [%4];" \
                 : "=r"(r0), "=r"(r1), "=r"(r2), "=r"(r3) : "r"(a))
#define MMA16816(d, a0, a1, a2, a3, b0, b1) \
    asm volatile("mma.sync.aligned.m16n8k16.row.col.f32.bf16.bf16.f32 " \
                 "{%0,%1,%2,%3}, {%4,%5,%6,%7}, {%8,%9}, {%0,%1,%2,%3};" \
                 : "+f"((d)[0]), "+f"((d)[1]), "+f"((d)[2]), "+f"((d)[3]) \
                 : "r"(a0), "r"(a1), "r"(a2), "r"(a3), "r"(b0), "r"(b1))

__device__ __forceinline__ uint32_t pack_bf16(float a, float b) {
    __nv_bfloat162 h = __floats2bfloat162_rn(a, b);
    return *(uint32_t*)&h;
}
// split 8 floats into bf16 hi + residual lo, packed as 4+4 b32
__device__ __forceinline__ void hilo8(const float* v, uint32_t* h, uint32_t* l) {
#pragma unroll
    for (int p = 0; p < 4; p++) {
        __nv_bfloat162 hh = __floats2bfloat162_rn(v[2*p], v[2*p+1]);
        float2 hf = __bfloat1622float2(hh);
        __nv_bfloat162 ll = __floats2bfloat162_rn(v[2*p] - hf.x, v[2*p+1] - hf.y);
        h[p] = *(uint32_t*)&hh;
        l[p] = *(uint32_t*)&ll;
    }
}

// fast exp via FMA poly (avoids MUFU bottleneck; |x| < ~80, rel err ~4e-5)
__device__ __forceinline__ float fexp(float x) {
    const float t = x * 1.4426950408889634f;
    const float n = rintf(t);
    const float r = t - n;
    float p = 0.009618130f;
    p = fmaf(p, r, 0.055504110f);
    p = fmaf(p, r, 0.240226507f);
    p = fmaf(p, r, 0.693147181f);
    p = fmaf(p, r, 1.0f);
    return __int_as_float(__float_as_int(p) + ((int)n << 23));
}

// ============================================================
// transpose: xT[b][n][ci] (bf16) from x[b][ci][n] (fp32)
// ============================================================
__global__ void __launch_bounds__(256) transpose_kernel(
    const float* __restrict__ x, __nv_bfloat16* __restrict__ xT)
{
    __shared__ float t[32][33];
    const int tx = threadIdx.x, ty = threadIdx.y;
    const int n0 = blockIdx.x * 32, ci0 = blockIdx.y * 32, b = blockIdx.z;
#pragma unroll
    for (int j = 0; j < 4; j++)
        t[ty + j * 8][tx] = x[((size_t)b * CC + ci0 + ty + j * 8) * NN + n0 + tx];
    __syncthreads();
#pragma unroll
    for (int j = 0; j < 4; j++) {
        const int n = n0 + ty + j * 8;
        xT[((size_t)b * NN + n) * CC + ci0 + tx] = __float2bfloat16(t[tx][ty + j * 8]);
    }
}

// ============================================================
// weight packing: Wt[t][co][ci] bf16 from w[co][ci][t] fp32
// ============================================================
__global__ void pack_wv_kernel(const float* __restrict__ wv,
                               __nv_bfloat16* __restrict__ Wt)
{
    const int i = blockIdx.x * 256 + threadIdx.x;   // 9*256*256
    const int t = i / (CC * CC);
    const int r = i % (CC * CC);
    const int co = r >> 8, ci = r & 255;
    Wt[i] = __float2bfloat16(wv[((size_t)co * CC + ci) * 9 + t]);
}
__global__ void pack_wqk_kernel(const float* __restrict__ wq,
                                const float* __restrict__ wk,
                                __nv_bfloat16* __restrict__ Wt)
{
    const int i = blockIdx.x * 256 + threadIdx.x;   // 9*64*256
    const int t = i / (64 * CC);
    const int r = i % (64 * CC);
    const int co = r >> 8, ci = r & 255;
    const float v = (co < 32) ? wq[((size_t)co * CC + ci) * 9 + t]
                              : wk[((size_t)(co - 32) * CC + ci) * 9 + t];
    Wt[i] = __float2bfloat16(v);
}

// ============================================================
// implicit-GEMM conv3x3 body via mma.sync, double-buffered A staging
// MODE 0: bf16 out [b][256][n] (V).
// MODE 1: Q/K conv; epilogue transposes + writes g_Qhl/g_Khl hi/lo.
// ============================================================
template<int COT, int MODE>
__device__ __forceinline__ void conv_body(
    int y0t, int cog, int b, uint8_t* dynsmem,
    const __nv_bfloat16* __restrict__ xT,
    const __nv_bfloat16* __restrict__ Wt,
    const float* __restrict__ bias0, const float* __restrict__ bias1,
    void* __restrict__ out0, void* __restrict__ out1)
{
    constexpr int COTOT = (MODE == 0) ? 256 : 64;   // Wt rows per tap
    constexpr int MW = COT / 32;     // m warps
    constexpr int NW = 8 / MW;       // n warps
    constexpr int NT = 128 / NW;     // warp n-tile (px)
    constexpr int NB8 = NT / 8;
    constexpr int NBG = NT / 16;

    const int tid = threadIdx.x;
    const int wid = tid >> 5, lid = tid & 31;
    const int wm = wid / NW, wn = wid % NW;
    const int y0 = y0t * 2;
    const int n0 = y0 * 64;
    const int co0 = cog * COT;

    const uint32_t sbase = (smem_u32(dynsmem) + 1023) & ~1023u;
    const uint32_t abase0 = sbase + 33792;
    const uint32_t abase1 = abase0 + COT * 128;

    // zero row at strip slot 256
    if (tid < 32) STS32U(sbase + 32768 + tid * 4, 0u);

    const int frow = lid & 15;
    const int fcb = (lid >> 4) * 16;

    float acc[2][NB8][4];
#pragma unroll
    for (int mt = 0; mt < 2; mt++)
#pragma unroll
        for (int nb = 0; nb < NB8; nb++)
#pragma unroll
            for (int i = 0; i < 4; i++) acc[mt][nb][i] = 0.f;

    // strip staging geometry: thread = one pixel slot (4 rows x 64 px)
    const int spx = tid & 63, sry = tid >> 6;
    const int sy = y0 - 1 + sry;
    const bool srow_ok = (sy >= 0) && (sy < HH);
    const uint8_t* xrow = (const uint8_t*)(xT +
        ((size_t)b * NN + (srow_ok ? sy : 0) * 64 + spx) * CC);

    auto stage_a = [&](int tap, int ci0, uint32_t ab) {
#pragma unroll
        for (int j = 0; j < COT / 32; j++) {
            const int i = j * 256 + tid;         // uint4 index
            const int row = i >> 3;
            const int cb = (i & 7) * 16;
            const uint8_t* src = (const uint8_t*)Wt +
                (((size_t)tap * COTOT + co0 + row) * CC + ci0) * 2 + cb;
            const uint4 d = *(const uint4*)src;
            STS128U(ab + SWZ((uint32_t)(row * 128 + cb)), d.x, d.y, d.z, d.w);
        }
    };

    for (int ci0 = 0; ci0 < CC; ci0 += 64) {
        // stage strip: 256 px x 64 ci (128B rows)
#pragma unroll
        for (int j = 0; j < 8; j++) {
            uint4 d = make_uint4(0, 0, 0, 0);
            if (srow_ok) d = *(const uint4*)(xrow + ci0 * 2 + j * 16);
            STS128U(sbase + SWZ((uint32_t)(tid * 128 + j * 16)), d.x, d.y, d.z, d.w);
        }
        stage_a(0, ci0, abase0);
        __syncthreads();   // strip + A(tap0) ready

        for (int tap = 0; tap < 9; tap++) {
            if (tap < 8) stage_a(tap + 1, ci0, (tap & 1) ? abase0 : abase1);
            const uint32_t ab = (tap & 1) ? abase1 : abase0;

            const int dy = tap / 3 - 1, dx = tap % 3 - 1;
            uint32_t brow[NBG];
#pragma unroll
            for (int g = 0; g < NBG; g++) {
                const int pn = wn * NT + g * 16 + frow;
                const int py = pn >> 6, px = pn & 63;
                const int yy = y0 + py + dy;
                const int xx = px + dx;
                const bool ok = (yy >= 0) && (yy < HH) && (xx >= 0) && (xx < WW);
                brow[g] = ok ? (uint32_t)(((py + dy + 1) * 64 + xx) * 128) : 32768u;
            }

#pragma unroll
            for (int ks = 0; ks < 4; ks++) {
                const uint32_t cib = ks * 32 + fcb;
                uint32_t Am[2][4];
#pragma unroll
                for (int mt = 0; mt < 2; mt++)
                    LDMX4(Am[mt][0], Am[mt][1], Am[mt][2], Am[mt][3],
                          ab + SWZ((uint32_t)((wm * 32 + mt * 16 + frow) * 128 + cib)));
                uint32_t Bf[NBG][4];
#pragma unroll
                for (int g = 0; g < NBG; g++)
                    LDMX4(Bf[g][0], Bf[g][1], Bf[g][2], Bf[g][3],
                          sbase + SWZ(brow[g] + cib));
#pragma unroll
                for (int mt = 0; mt < 2; mt++)
#pragma unroll
                    for (int g = 0; g < NBG; g++) {
                        MMA16816(acc[mt][2 * g],     Am[mt][0], Am[mt][1], Am[mt][2], Am[mt][3],
                                 Bf[g][0], Bf[g][2]);
                        MMA16816(acc[mt][2 * g + 1], Am[mt][0], Am[mt][1], Am[mt][2], Am[mt][3],
                                 Bf[g][1], Bf[g][3]);
                    }
            }
            __syncthreads();   // A(tap+1) ready; mma(tap) done before buf reuse
        }
    }

    // epilogue
    const int er = lid >> 2, ec = (lid & 3) * 2;
    if (MODE == 0) {
        __nv_bfloat16* ov = (__nv_bfloat16*)out0;
#pragma unroll
        for (int mt = 0; mt < 2; mt++)
#pragma unroll
            for (int h = 0; h < 2; h++) {
                const int co = wm * 32 + mt * 16 + er + h * 8;
                const float bb = bias0[co0 + co];
#pragma unroll
                for (int nb = 0; nb < NB8; nb++) {
                    const int n = n0 + wn * NT + nb * 8 + ec;
                    const uint32_t pk = pack_bf16(acc[mt][nb][h * 2] + bb,
                                                  acc[mt][nb][h * 2 + 1] + bb);
                    *(uint32_t*)&ov[((size_t)b * CC + co0 + co) * NN + n] = pk;
                }
            }
    } else {
        // MODE 1: transpose via smem (reuse strip area as fp32 [64][132]),
        // then write hi/lo rows of g_Qhl (d 0-31) / g_Khl (d 32-63).
        float* sval = (float*)dynsmem;   // use raw; address via sbase arithmetic
        // use sbase region: float index helper
        // store fragments with bias
#pragma unroll
        for (int mt = 0; mt < 2; mt++)
#pragma unroll
            for (int h = 0; h < 2; h++) {
                const int co = wm * 32 + mt * 16 + er + h * 8;
                const float bb = (co < 32) ? bias0[co] : bias1[co - 32];
#pragma unroll
                for (int nb = 0; nb < NB8; nb++) {
                    const int nl = wn * NT + nb * 8 + ec;
                    const uint32_t a0 = sbase + (uint32_t)((co * 132 + nl) * 4);
                    *(float*)((uint8_t*)sval + (a0 - smem_u32(sval))) = 0.f; // dummy avoid
                    STS32U(a0, __float_as_uint(acc[mt][nb][h * 2] + bb));
                    STS32U(a0 + 4, __float_as_uint(acc[mt][nb][h * 2 + 1] + bb));
                }
            }
        __syncthreads();

        const int n = tid & 127;
        const int dbase = (tid >> 7) * 32;
        uint8_t* base = (uint8_t*)((tid < 128) ? out0 : out1);
        uint8_t* row = base + ((size_t)b * NN + n0 + n) * 128;
#pragma unroll
        for (int g = 0; g < 4; g++) {
            float v[8];
#pragma unroll
            for (int i = 0; i < 8; i++) {
                uint32_t u;
                asm volatile("ld.shared.b32 %0, [%1];" : "=r"(u)
                    : "r"(sbase + (uint32_t)(((dbase + g * 8 + i) * 132 + n) * 4)));
                v[i] = __uint_as_float(u);
            }
            uint32_t hh[4], ll[4];
            hilo8(v, hh, ll);
            *(uint4*)(row + g * 16)      = make_uint4(hh[0], hh[1], hh[2], hh[3]);
            *(uint4*)(row + 64 + g * 16) = make_uint4(ll[0], ll[1], ll[2], ll[3]);
        }
    }
}

// ============================================================
// qk body: P[b][k][q] = exp(S), S = K.Q^T via bf16 hi/lo 3-chain mma.
// Double-buffered sQ/sP, 1 sync per chunk. k-tile 128, q-half 2048.
// ============================================================
__device__ __forceinline__ void qk_body(int k0, int qh, int b, uint8_t* dynq)
{
    const uint32_t kb  = (smem_u32(dynq) + 1023) & ~1023u;
    const uint32_t qb0 = kb + 16384;
    const uint32_t qb1 = qb0 + 8192;
    const uint32_t pb0 = qb1 + 8192;
    const uint32_t pb1 = pb0 + 16384;

    const int tid = threadIdx.x, wid = tid >> 5, lid = tid & 31;

    // stage K tile (pure copy: layout already [k][hi|lo])
    {
        const uint8_t* Ks = (const uint8_t*)g_Khl + ((size_t)b * NN + k0) * 128;
        const int r = tid >> 1, seg = (tid & 1) * 64;
#pragma unroll
        for (int j = 0; j < 4; j++) {
            const uint4 d = *(const uint4*)(Ks + (size_t)r * 128 + seg + j * 16);
            STS128U(kb + SWZ((uint32_t)(r * 128 + seg + j * 16)), d.x, d.y, d.z, d.w);
        }
    }

    const uint8_t* Qs = (const uint8_t*)g_Qhl +
                        ((size_t)b * NN + (size_t)qh * (NN / 2)) * 128;
    __nv_bfloat16* Pb = g_P + (size_t)b * NN * NN;

    const int frow = lid & 15, fhc = (lid >> 4) * 16;
    const int er = lid >> 2, ec = (lid & 3) * 2;
    const int sqr = tid >> 2, sqseg = (tid & 3) * 32;
    const int cpr = tid >> 1, cpseg = (tid & 1) * 64;

    float l0 = 0.f, l1 = 0.f;

    uint4 qpre[2];
#pragma unroll
    for (int j = 0; j < 2; j++)
        qpre[j] = *(const uint4*)(Qs + (size_t)sqr * 128 + sqseg + j * 16);

    for (int cn = 0; cn < NN / 128; cn++) {      // 32 chunks of 64 q
        const uint32_t qb = (cn & 1) ? qb1 : qb0;
        const uint32_t pb = (cn & 1) ? pb1 : pb0;

#pragma unroll
        for (int j = 0; j < 2; j++)
            STS128U(qb + SWZ((uint32_t)(sqr * 128 + sqseg + j * 16)),
                    qpre[j].x, qpre[j].y, qpre[j].z, qpre[j].w);
        if (cn + 1 < NN / 128) {
#pragma unroll
            for (int j = 0; j < 2; j++)
                qpre[j] = *(const uint4*)(Qs + (size_t)((cn + 1) * 64 + sqr) * 128
                                          + sqseg + j * 16);
        }
        __syncthreads();   // qbuf[cn] ready; pbuf[cn-1] exp-stores complete

        if (cn > 0) {
            const uint32_t pprev = (cn & 1) ? pb0 : pb1;
            const size_t qc = (size_t)qh * (NN / 2) + (size_t)(cn - 1) * 64;
            uint8_t* dst = (uint8_t*)(Pb + (size_t)(k0 + cpr) * NN + qc) + cpseg;
#pragma unroll
            for (int j = 0; j < 4; j++) {
                uint32_t a, b2, c, d;
                LDS128U(a, b2, c, d, pprev + SWZ((uint32_t)(cpr * 128 + cpseg + j * 16)));
                *(uint4*)(dst + j * 16) = make_uint4(a, b2, c, d);
            }
        }

        float sa[8][4];
#pragma unroll
        for (int i = 0; i < 8; i++)
#pragma unroll
            for (int j = 0; j < 4; j++) sa[i][j] = 0.f;

#pragma unroll
        for (int s = 0; s < 2; s++) {
            uint32_t Ah[4], Al[4];
            LDMX4(Ah[0], Ah[1], Ah[2], Ah[3],
                  kb + SWZ((uint32_t)((wid * 16 + frow) * 128 + s * 32 + fhc)));
            LDMX4(Al[0], Al[1], Al[2], Al[3],
                  kb + SWZ((uint32_t)((wid * 16 + frow) * 128 + 64 + s * 32 + fhc)));
#pragma unroll
            for (int qg = 0; qg < 4; qg++) {
                uint32_t Bh[4], Bl[4];
                LDMX4(Bh[0], Bh[1], Bh[2], Bh[3],
                      qb + SWZ((uint32_t)((qg * 16 + frow) * 128 + s * 32 + fhc)));
                LDMX4(Bl[0], Bl[1], Bl[2], Bl[3],
                      qb + SWZ((uint32_t)((qg * 16 + frow) * 128 + 64 + s * 32 + fhc)));
                MMA16816(sa[qg*2+0], Ah[0], Ah[1], Ah[2], Ah[3], Bh[0], Bh[2]);
                MMA16816(sa[qg*2+1], Ah[0], Ah[1], Ah[2], Ah[3], Bh[1], Bh[3]);
                MMA16816(sa[qg*2+0], Ah[0], Ah[1], Ah[2], Ah[3], Bl[0], Bl[2]);
                MMA16816(sa[qg*2+1], Ah[0], Ah[1], Ah[2], Ah[3], Bl[1], Bl[3]);
                MMA16816(sa[qg*2+0], Al[0], Al[1], Al[2], Al[3], Bh[0], Bh[2]);
                MMA16816(sa[qg*2+1], Al[0], Al[1], Al[2], Al[3], Bh[1], Bh[3]);
            }
        }

#pragma unroll
        for (int n8 = 0; n8 < 8; n8++) {
            const float e0 = fexp(sa[n8][0]);
            const float e1 = fexp(sa[n8][1]);
            const float e2 = fexp(sa[n8][2]);
            const float e3 = fexp(sa[n8][3]);
            l0 += e0 + e1;
            l1 += e2 + e3;
            const int qq = n8 * 8 + ec;
            STS32U(pb + SWZ((uint32_t)((wid * 16 + er) * 128 + qq * 2)),
                   pack_bf16(e0, e1));
            STS32U(pb + SWZ((uint32_t)((wid * 16 + er + 8) * 128 + qq * 2)),
                   pack_bf16(e2, e3));
        }
    }

    __syncthreads();   // last pbuf complete
    {
        const int cn = NN / 128 - 1;
        const uint32_t plast = (cn & 1) ? pb1 : pb0;
        const size_t qc = (size_t)qh * (NN / 2) + (size_t)cn * 64;
        uint8_t* dst = (uint8_t*)(Pb + (size_t)(k0 + cpr) * NN + qc) + cpseg;
#pragma unroll
        for (int j = 0; j < 4; j++) {
            uint32_t a, b2, c, d;
            LDS128U(a, b2, c, d, plast + SWZ((uint32_t)(cpr * 128 + cpseg + j * 16)));
            *(uint4*)(dst + j * 16) = make_uint4(a, b2, c, d);
        }
    }

    l0 += __shfl_xor_sync(0xFFFFFFFF, l0, 1);
    l0 += __shfl_xor_sync(0xFFFFFFFF, l0, 2);
    l1 += __shfl_xor_sync(0xFFFFFFFF, l1, 1);
    l1 += __shfl_xor_sync(0xFFFFFFFF, l1, 2);
    if ((lid & 3) == 0) {
        g_Lpart[((size_t)b * NN + k0 + wid * 16 + er) * 2 + qh]     = l0;
        g_Lpart[((size_t)b * NN + k0 + wid * 16 + er + 8) * 2 + qh] = l1;
    }
}

// ============================================================
// conv-QK standalone (writes Qhl/Khl directly)
// ============================================================
__global__ void __launch_bounds__(256) convqk_kernel(
    const __nv_bfloat16* __restrict__ xT,
    const __nv_bfloat16* __restrict__ Wt,
    const float* __restrict__ bq, const float* __restrict__ bk,
    __nv_bfloat16* __restrict__ Qhl, __nv_bfloat16* __restrict__ Khl)
{
    extern __shared__ uint8_t dynsmem[];
    conv_body<64, 1>(blockIdx.x, 0, blockIdx.y, dynsmem,
                     xT, Wt, bq, bk, Qhl, Khl);
}

// ============================================================
// fused: blocks 0..255 = conv-V, blocks 256..511 = qk attention
// ============================================================
__global__ void __launch_bounds__(256) fused_vqk_kernel(
    const __nv_bfloat16* __restrict__ xT,
    const __nv_bfloat16* __restrict__ WtV,
    const float* __restrict__ bv,
    __nv_bfloat16* __restrict__ Vbf)
{
    extern __shared__ uint8_t dynsmem[];
    const int bx = blockIdx.x;
    if (bx < 256) {
        conv_body<128, 0>(bx & 31, (bx >> 5) & 1, bx >> 6, dynsmem,
                          xT, WtV, bv, nullptr, Vbf, nullptr);
    } else {
        const int i = bx - 256;
        qk_body((i & 31) * 128, (i >> 5) & 1, i >> 6, dynsmem);
    }
}

// ============================================================
// OV via mma.sync: D[c,k] = sum_q V[c,q]*P[k,q]
// Double-buffered A/B tiles, 1 sync per chunk.
// Block tile: 128 c x 128 k, q-chunks 64. 8 warps = 4(m) x 2(n).
// out = x + gamma * (1/L[k]) * D
// ============================================================
__global__ void __launch_bounds__(256) ov_mma_kernel(
    const float* __restrict__ x, const float* __restrict__ gamma,
    float* __restrict__ out)
{
    extern __shared__ uint8_t dyno[];
    __shared__ float Lsh[128];

    const uint32_t ab0 = (smem_u32(dyno) + 1023) & ~1023u;
    const uint32_t ab1 = ab0 + 16384;
    const uint32_t bb0 = ab1 + 16384;
    const uint32_t bb1 = bb0 + 16384;

    const int tid = threadIdx.x;
    const int wid = tid >> 5;
    const int lid = tid & 31;
    const int wm = wid >> 1;            // 0..3 : c block of 32
    const int wn = wid & 1;             // 0..1 : k block of 64
    const int k0 = blockIdx.x * 128;
    const int c0 = blockIdx.y * 128;
    const int b  = blockIdx.z;

    if (tid < 128) {
        const float2 lp = *(const float2*)&g_Lpart[((size_t)b * NN + k0 + tid) * 2];
        Lsh[tid] = 1.f / (lp.x + lp.y);
    }

    const __nv_bfloat16* Vg = g_Vbf + ((size_t)b * CC + c0) * NN;
    const __nv_bfloat16* Pg = g_P + (size_t)b * NN * NN;

    const int srow = tid >> 1;          // 0..127
    const int qo = (tid & 1) * 32;      // element offset (half row)

    uint4 a_pre[4], b_pre[4];
#pragma unroll
    for (int j = 0; j < 4; j++) {
        a_pre[j] = *(const uint4*)&Vg[(size_t)srow * NN + qo + j * 8];
        b_pre[j] = *(const uint4*)&Pg[(size_t)(k0 + srow) * NN + qo + j * 8];
    }

    float acc[2][8][4];
#pragma unroll
    for (int mt = 0; mt < 2; mt++)
#pragma unroll
        for (int nt = 0; nt < 8; nt++)
#pragma unroll
            for (int i = 0; i < 4; i++) acc[mt][nt][i] = 0.f;

    const int frow = lid & 15;
    const int fcb  = (lid >> 4) * 16;

    for (int chunk = 0; chunk < NN / 64; chunk++) {
        const uint32_t abase = (chunk & 1) ? ab1 : ab0;
        const uint32_t bbase = (chunk & 1) ? bb1 : bb0;

#pragma unroll
        for (int j = 0; j < 4; j++) {
            STS128U(abase + SWZ((uint32_t)(srow * 128 + qo * 2 + j * 16)),
                    a_pre[j].x, a_pre[j].y, a_pre[j].z, a_pre[j].w);
            STS128U(bbase + SWZ((uint32_t)(srow * 128 + qo * 2 + j * 16)),
                    b_pre[j].x, b_pre[j].y, b_pre[j].z, b_pre[j].w);
        }
        if (chunk + 1 < NN / 64) {
            const int qc = (chunk + 1) * 64;
#pragma unroll
            for (int j = 0; j < 4; j++) {
                a_pre[j] = *(const uint4*)&Vg[(size_t)srow * NN + qc + qo + j * 8];
                b_pre[j] = *(const uint4*)&Pg[(size_t)(k0 + srow) * NN + qc + qo + j * 8];
            }
        }
        __syncthreads();   // buf[chunk] ready (and mma[chunk-2] long done)

#pragma unroll
        for (int ks = 0; ks < 4; ks++) {
            const uint32_t cib = ks * 32 + fcb;
            uint32_t Am[2][4];
#pragma unroll
            for (int mt = 0; mt < 2; mt++)
                LDMX4(Am[mt][0], Am[mt][1], Am[mt][2], Am[mt][3],
                      abase + SWZ((uint32_t)((wm * 32 + mt * 16 + frow) * 128 + cib)));
            uint32_t Bf[4][4];
#pragma unroll
            for (int g = 0; g < 4; g++)
                LDMX4(Bf[g][0], Bf[g][1], Bf[g][2], Bf[g][3],
                      bbase + SWZ((uint32_t)((wn * 64 + g * 16 + frow) * 128 + cib)));
#pragma unroll
            for (int mt = 0; mt < 2; mt++)
#pragma unroll
                for (int g = 0; g < 4; g++) {
                    MMA16816(acc[mt][2 * g],     Am[mt][0], Am[mt][1], Am[mt][2], Am[mt][3],
                             Bf[g][0], Bf[g][2]);
                    MMA16816(acc[mt][2 * g + 1], Am[mt][0], Am[mt][1], Am[mt][2], Am[mt][3],
                             Bf[g][1], Bf[g][3]);
                }
        }
    }

    // epilogue: out = x + g * Linv[k] * D
    const float g = gamma[0];
    const int er = lid >> 2;
    const int ec = (lid & 3) * 2;
#pragma unroll
    for (int mt = 0; mt < 2; mt++) {
#pragma unroll
        for (int nt = 0; nt < 8; nt++) {
            const int kk = wn * 64 + nt * 8 + ec;
            const float l0 = Lsh[kk], l1 = Lsh[kk + 1];
#pragma unroll
            for (int h = 0; h < 2; h++) {
                const int c = c0 + wm * 32 + mt * 16 + er + h * 8;
                const size_t idx = ((size_t)b * CC + c) * NN + k0 + kk;
                const float2 xv = *(const float2*)&x[idx];
                float2 o;
                o.x = xv.x + g * l0 * acc[mt][nt][h * 2 + 0];
                o.y = xv.y + g * l1 * acc[mt][nt][h * 2 + 1];
                *(float2*)&out[idx] = o;
            }
        }
    }
}

// ============================================================
extern "C" void kernel_launch(void* const* d_in, const int* in_sizes, int n_in,
                              void* d_out, int out_size)
{
    const float* x     = (const float*)d_in[0];
    const float* wq    = (const float*)d_in[1];
    const float* bq    = (const float*)d_in[2];
    const float* wk    = (const float*)d_in[3];
    const float* bk    = (const float*)d_in[4];
    const float* wv    = (const float*)d_in[5];
    const float* bv    = (const float*)d_in[6];
    const float* gamma = (const float*)d_in[7];
    float* out = (float*)d_out;

    __nv_bfloat16 *Vbp, *xTp, *WtVp, *WtQKp, *Qhlp, *Khlp;
    cudaGetSymbolAddress((void**)&Vbp, g_Vbf);
    cudaGetSymbolAddress((void**)&xTp, g_xT);
    cudaGetSymbolAddress((void**)&WtVp, g_WtV);
    cudaGetSymbolAddress((void**)&WtQKp, g_WtQK);
    cudaGetSymbolAddress((void**)&Qhlp, g_Qhl);
    cudaGetSymbolAddress((void**)&Khlp, g_Khl);

    static int attr_set = 0;
    const int SMQK  = 1024 + 33792 + 2 * 8192;    // 51200 (convqk)
    const int SMFUS = 1024 + 33792 + 2 * 16384;   // 67584 (fused: max of both paths)
    const int SMOV  = 1024 + 4 * 16384;           // 66560
    if (!attr_set) {
        cudaFuncSetAttribute(convqk_kernel,
                             cudaFuncAttributeMaxDynamicSharedMemorySize, SMQK);
        cudaFuncSetAttribute(fused_vqk_kernel,
                             cudaFuncAttributeMaxDynamicSharedMemorySize, SMFUS);
        cudaFuncSetAttribute(ov_mma_kernel,
                             cudaFuncAttributeMaxDynamicSharedMemorySize, SMOV);
        attr_set = 1;
    }

    transpose_kernel<<<dim3(NN / 32, CC / 32, BB), dim3(32, 8)>>>(x, xTp);
    pack_wv_kernel<<<(9 * CC * CC) / 256, 256>>>(wv, WtVp);
    pack_wqk_kernel<<<(9 * 64 * CC) / 256, 256>>>(wq, wk, WtQKp);

    convqk_kernel<<<dim3(32, BB), 256, SMQK>>>(xTp, WtQKp, bq, bk, Qhlp, Khlp);
    fused_vqk_kernel<<<512, 256, SMFUS>>>(xTp, WtVp, bv, Vbp);
    ov_mma_kernel<<<dim3(NN / 128, CC / 128, BB), 256, SMOV>>>(x, gamma, out);
}

// round 17
// speedup vs baseline: 1.5894x; 1.5894x over previous
#include <cuda_runtime.h>
#include <cuda_bf16.h>
#include <stdint.h>
#include <math.h>

#define BB 4
#define CC 256
#define HH 64
#define WW 64
#define NN (HH*WW)      // 4096
#define CQK 32

// ---- scratch (static device globals; no allocation) ----
__device__ float g_Q[BB*CQK*NN];                    // 2 MB   [b][d][n] (conv out)
__device__ float g_K[BB*CQK*NN];                    // 2 MB   [b][d][n] (conv out)
__device__ __nv_bfloat16 g_Qhl[BB*NN*64];           // 2 MB   [b][n][hi d0..31 | lo d0..31]
__device__ __nv_bfloat16 g_Khl[BB*NN*64];           // 2 MB   [b][n][hi | lo]
__device__ __nv_bfloat16 g_Vbf[BB*CC*NN];           // 8 MB   [b][c][n]
__device__ __nv_bfloat16 g_P[(size_t)BB*NN*NN];     // 128 MB P=exp(S^T): [b][k][q]
__device__ float g_Lpart[BB*NN*2];                  // partial col sums (per k, q-half)
__device__ __nv_bfloat16 g_xT[(size_t)BB*NN*CC];    // 8 MB   xT: [b][n][ci]
__device__ __nv_bfloat16 g_WtV[9*CC*CC];            // 1.1 MB [t][co][ci]
__device__ __nv_bfloat16 g_WtQK[9*64*CC];           // 288 KB [t][co(q0-31,k32-63)][ci]

// ============================================================
// helpers
// ============================================================
__device__ __forceinline__ uint32_t smem_u32(const void* p) {
    uint32_t a;
    asm("{ .reg .u64 t; cvta.to.shared.u64 t, %1; cvt.u32.u64 %0, t; }"
        : "=r"(a) : "l"(p));
    return a;
}
#define SWZ(x) ((x) ^ (((x) >> 3) & 0x70))
#define STS128U(addr, a, b, c, d) \
    asm volatile("st.shared.v4.b32 [%0], {%1, %2, %3, %4};" \
                 :: "r"(addr), "r"(a), "r"(b), "r"(c), "r"(d) : "memory")
#define STS32U(addr, a) \
    asm volatile("st.shared.b32 [%0], %1;" :: "r"(addr), "r"(a) : "memory")
#define LDS128U(r0, r1, r2, r3, addr) \
    asm volatile("ld.shared.v4.b32 {%0,%1,%2,%3}, [%4];" \
                 : "=r"(r0), "=r"(r1), "=r"(r2), "=r"(r3) : "r"(addr))
#define LDMX4(r0, r1, r2, r3, a) \
    asm volatile("ldmatrix.sync.aligned.m8n8.x4.shared.b16 {%0,%1,%2,%3}, [%4];" \
                 : "=r"(r0), "=r"(r1), "=r"(r2), "=r"(r3) : "r"(a))
#define MMA16816(d, a0, a1, a2, a3, b0, b1) \
    asm volatile("mma.sync.aligned.m16n8k16.row.col.f32.bf16.bf16.f32 " \
                 "{%0,%1,%2,%3}, {%4,%5,%6,%7}, {%8,%9}, {%0,%1,%2,%3};" \
                 : "+f"((d)[0]), "+f"((d)[1]), "+f"((d)[2]), "+f"((d)[3]) \
                 : "r"(a0), "r"(a1), "r"(a2), "r"(a3), "r"(b0), "r"(b1))

__device__ __forceinline__ uint32_t pack_bf16(float a, float b) {
    __nv_bfloat162 h = __floats2bfloat162_rn(a, b);
    return *(uint32_t*)&h;
}
// split 8 floats into bf16 hi + residual lo, packed as 4+4 b32
__device__ __forceinline__ void hilo8(const float* v, uint32_t* h, uint32_t* l) {
#pragma unroll
    for (int p = 0; p < 4; p++) {
        __nv_bfloat162 hh = __floats2bfloat162_rn(v[2*p], v[2*p+1]);
        float2 hf = __bfloat1622float2(hh);
        __nv_bfloat162 ll = __floats2bfloat162_rn(v[2*p] - hf.x, v[2*p+1] - hf.y);
        h[p] = *(uint32_t*)&hh;
        l[p] = *(uint32_t*)&ll;
    }
}

// fast exp via FMA poly (avoids MUFU bottleneck; |x| < ~80, rel err ~4e-5)
__device__ __forceinline__ float fexp(float x) {
    const float t = x * 1.4426950408889634f;
    const float n = rintf(t);
    const float r = t - n;
    float p = 0.009618130f;
    p = fmaf(p, r, 0.055504110f);
    p = fmaf(p, r, 0.240226507f);
    p = fmaf(p, r, 0.693147181f);
    p = fmaf(p, r, 1.0f);
    return __int_as_float(__float_as_int(p) + ((int)n << 23));
}

// ============================================================
// transpose: xT[b][n][ci] (bf16) from x[b][ci][n] (fp32)
// ============================================================
__global__ void __launch_bounds__(256) transpose_kernel(
    const float* __restrict__ x, __nv_bfloat16* __restrict__ xT)
{
    __shared__ float t[32][33];
    const int tx = threadIdx.x, ty = threadIdx.y;
    const int n0 = blockIdx.x * 32, ci0 = blockIdx.y * 32, b = blockIdx.z;
#pragma unroll
    for (int j = 0; j < 4; j++)
        t[ty + j * 8][tx] = x[((size_t)b * CC + ci0 + ty + j * 8) * NN + n0 + tx];
    __syncthreads();
#pragma unroll
    for (int j = 0; j < 4; j++) {
        const int n = n0 + ty + j * 8;
        xT[((size_t)b * NN + n) * CC + ci0 + tx] = __float2bfloat16(t[tx][ty + j * 8]);
    }
}

// ============================================================
// weight packing: Wt[t][co][ci] bf16 from w[co][ci][t] fp32
// ============================================================
__global__ void pack_wv_kernel(const float* __restrict__ wv,
                               __nv_bfloat16* __restrict__ Wt)
{
    const int i = blockIdx.x * 256 + threadIdx.x;   // 9*256*256
    const int t = i / (CC * CC);
    const int r = i % (CC * CC);
    const int co = r >> 8, ci = r & 255;
    Wt[i] = __float2bfloat16(wv[((size_t)co * CC + ci) * 9 + t]);
}
__global__ void pack_wqk_kernel(const float* __restrict__ wq,
                                const float* __restrict__ wk,
                                __nv_bfloat16* __restrict__ Wt)
{
    const int i = blockIdx.x * 256 + threadIdx.x;   // 9*64*256
    const int t = i / (64 * CC);
    const int r = i % (64 * CC);
    const int co = r >> 8, ci = r & 255;
    const float v = (co < 32) ? wq[((size_t)co * CC + ci) * 9 + t]
                              : wk[((size_t)(co - 32) * CC + ci) * 9 + t];
    Wt[i] = __float2bfloat16(v);
}

// ============================================================
// qkpack: fp32 [b][d][n] -> bf16 hi/lo [b][n][hi32|lo32]
// ============================================================
__global__ void __launch_bounds__(256) qkpack_kernel()
{
    __shared__ float t[32][65];
    const int tid = threadIdx.x;
    const int n0 = blockIdx.x * 64;
    const int sel = blockIdx.y;
    const int b = blockIdx.z;
    const float* src = (sel ? g_K : g_Q) + (size_t)b * CQK * NN;
    uint8_t* dst = (uint8_t*)((sel ? g_Khl : g_Qhl) + (size_t)b * NN * 64);

    const int d = tid >> 3, ng = (tid & 7) * 8;
    const float4 f0 = *(const float4*)&src[(size_t)d * NN + n0 + ng];
    const float4 f1 = *(const float4*)&src[(size_t)d * NN + n0 + ng + 4];
    t[d][ng + 0] = f0.x; t[d][ng + 1] = f0.y; t[d][ng + 2] = f0.z; t[d][ng + 3] = f0.w;
    t[d][ng + 4] = f1.x; t[d][ng + 5] = f1.y; t[d][ng + 6] = f1.z; t[d][ng + 7] = f1.w;
    __syncthreads();

    const int n = tid >> 2, dg = (tid & 3) * 8;
    float v[8];
#pragma unroll
    for (int i = 0; i < 8; i++) v[i] = t[dg + i][n];
    uint32_t h[4], l[4];
    hilo8(v, h, l);
    uint8_t* row = dst + (size_t)(n0 + n) * 128;
    *(uint4*)(row + dg * 2)      = make_uint4(h[0], h[1], h[2], h[3]);
    *(uint4*)(row + 64 + dg * 2) = make_uint4(l[0], l[1], l[2], l[3]);
}

// ============================================================
// implicit-GEMM conv3x3 via mma.sync, double-buffered A staging
// MODE 0: bf16 out [b][256][n] (V).  MODE 1: fp32 split q/k [b][32][n].
// ============================================================
template<int COT, int MODE>
__global__ void __launch_bounds__(256) conv_mma_kernel(
    const __nv_bfloat16* __restrict__ xT,
    const __nv_bfloat16* __restrict__ Wt,
    const float* __restrict__ bias0, const float* __restrict__ bias1,
    void* __restrict__ out0, void* __restrict__ out1)
{
    extern __shared__ uint8_t dynsmem[];
    constexpr int COTOT = (MODE == 0) ? 256 : 64;   // Wt rows per tap
    constexpr int MW = COT / 32;     // m warps
    constexpr int NW = 8 / MW;       // n warps
    constexpr int NT = 128 / NW;     // warp n-tile (px)
    constexpr int NB8 = NT / 8;
    constexpr int NBG = NT / 16;

    const int tid = threadIdx.x;
    const int wid = tid >> 5, lid = tid & 31;
    const int wm = wid / NW, wn = wid % NW;
    const int y0 = blockIdx.x * 2;
    const int n0 = y0 * 64;
    const int co0 = blockIdx.y * COT;
    const int b = blockIdx.z;

    const uint32_t sbase = (smem_u32(dynsmem) + 1023) & ~1023u;
    const uint32_t abase0 = sbase + 33792;
    const uint32_t abase1 = abase0 + COT * 128;

    // zero row at strip slot 256
    if (tid < 32) STS32U(sbase + 32768 + tid * 4, 0u);

    const int frow = lid & 15;
    const int fcb = (lid >> 4) * 16;

    float acc[2][NB8][4];
#pragma unroll
    for (int mt = 0; mt < 2; mt++)
#pragma unroll
        for (int nb = 0; nb < NB8; nb++)
#pragma unroll
            for (int i = 0; i < 4; i++) acc[mt][nb][i] = 0.f;

    // strip staging geometry: thread = one pixel slot (4 rows x 64 px)
    const int spx = tid & 63, sry = tid >> 6;
    const int sy = y0 - 1 + sry;
    const bool srow_ok = (sy >= 0) && (sy < HH);
    const uint8_t* xrow = (const uint8_t*)(xT +
        ((size_t)b * NN + (srow_ok ? sy : 0) * 64 + spx) * CC);

    auto stage_a = [&](int tap, int ci0, uint32_t ab) {
#pragma unroll
        for (int j = 0; j < COT / 32; j++) {
            const int i = j * 256 + tid;         // uint4 index
            const int row = i >> 3;
            const int cb = (i & 7) * 16;
            const uint8_t* src = (const uint8_t*)Wt +
                (((size_t)tap * COTOT + co0 + row) * CC + ci0) * 2 + cb;
            const uint4 d = *(const uint4*)src;
            STS128U(ab + SWZ((uint32_t)(row * 128 + cb)), d.x, d.y, d.z, d.w);
        }
    };

    for (int ci0 = 0; ci0 < CC; ci0 += 64) {
        // stage strip: 256 px x 64 ci (128B rows). Safe: last tap's sync of
        // previous chunk guarantees all mma reads of strip completed.
#pragma unroll
        for (int j = 0; j < 8; j++) {
            uint4 d = make_uint4(0, 0, 0, 0);
            if (srow_ok) d = *(const uint4*)(xrow + ci0 * 2 + j * 16);
            STS128U(sbase + SWZ((uint32_t)(tid * 128 + j * 16)), d.x, d.y, d.z, d.w);
        }
        stage_a(0, ci0, abase0);
        __syncthreads();   // strip + A(tap0) ready (also covers zero-row, 1st iter)

        for (int tap = 0; tap < 9; tap++) {
            // stage next tap's A into the other buffer (overlaps mma below)
            if (tap < 8) stage_a(tap + 1, ci0, (tap & 1) ? abase0 : abase1);
            const uint32_t ab = (tap & 1) ? abase1 : abase0;

            // per-lane B row bases for this tap (boundary -> zero row)
            const int dy = tap / 3 - 1, dx = tap % 3 - 1;
            uint32_t brow[NBG];
#pragma unroll
            for (int g = 0; g < NBG; g++) {
                const int pn = wn * NT + g * 16 + frow;
                const int py = pn >> 6, px = pn & 63;
                const int yy = y0 + py + dy;
                const int xx = px + dx;
                const bool ok = (yy >= 0) && (yy < HH) && (xx >= 0) && (xx < WW);
                brow[g] = ok ? (uint32_t)(((py + dy + 1) * 64 + xx) * 128) : 32768u;
            }

#pragma unroll
            for (int ks = 0; ks < 4; ks++) {
                const uint32_t cib = ks * 32 + fcb;
                uint32_t Am[2][4];
#pragma unroll
                for (int mt = 0; mt < 2; mt++)
                    LDMX4(Am[mt][0], Am[mt][1], Am[mt][2], Am[mt][3],
                          ab + SWZ((uint32_t)((wm * 32 + mt * 16 + frow) * 128 + cib)));
                uint32_t Bf[NBG][4];
#pragma unroll
                for (int g = 0; g < NBG; g++)
                    LDMX4(Bf[g][0], Bf[g][1], Bf[g][2], Bf[g][3],
                          sbase + SWZ(brow[g] + cib));
#pragma unroll
                for (int mt = 0; mt < 2; mt++)
#pragma unroll
                    for (int g = 0; g < NBG; g++) {
                        MMA16816(acc[mt][2 * g],     Am[mt][0], Am[mt][1], Am[mt][2], Am[mt][3],
                                 Bf[g][0], Bf[g][2]);
                        MMA16816(acc[mt][2 * g + 1], Am[mt][0], Am[mt][1], Am[mt][2], Am[mt][3],
                                 Bf[g][1], Bf[g][3]);
                    }
            }
            __syncthreads();   // A(tap+1) ready; mma(tap) done before buf reuse
        }
    }

    // epilogue
    const int er = lid >> 2, ec = (lid & 3) * 2;
    if (MODE == 0) {
        __nv_bfloat16* ov = (__nv_bfloat16*)out0;
#pragma unroll
        for (int mt = 0; mt < 2; mt++)
#pragma unroll
            for (int h = 0; h < 2; h++) {
                const int co = wm * 32 + mt * 16 + er + h * 8;
                const float bb = bias0[co0 + co];
#pragma unroll
                for (int nb = 0; nb < NB8; nb++) {
                    const int n = n0 + wn * NT + nb * 8 + ec;
                    const uint32_t pk = pack_bf16(acc[mt][nb][h * 2] + bb,
                                                  acc[mt][nb][h * 2 + 1] + bb);
                    *(uint32_t*)&ov[((size_t)b * CC + co0 + co) * NN + n] = pk;
                }
            }
    } else {
#pragma unroll
        for (int mt = 0; mt < 2; mt++)
#pragma unroll
            for (int h = 0; h < 2; h++) {
                const int co = wm * 32 + mt * 16 + er + h * 8;
                float* dst; int d; float bb;
                if (co < 32) { dst = (float*)out0; d = co;      bb = bias0[d]; }
                else         { dst = (float*)out1; d = co - 32; bb = bias1[d]; }
#pragma unroll
                for (int nb = 0; nb < NB8; nb++) {
                    const int n = n0 + wn * NT + nb * 8 + ec;
                    float2 o;
                    o.x = acc[mt][nb][h * 2] + bb;
                    o.y = acc[mt][nb][h * 2 + 1] + bb;
                    *(float2*)&dst[((size_t)b * CQK + d) * NN + n] = o;
                }
            }
    }
}

// ============================================================
// qk_mma: P[b][k][q] = exp(S), S = K.Q^T via bf16 hi/lo 3-chain mma.
// Double-buffered sQ/sP, 1 sync per chunk.
// Block: k-tile 128 (8 warps x 16 k), q-half 2048 in chunks of 64.
// ============================================================
__global__ void __launch_bounds__(256) qk_mma_kernel()
{
    extern __shared__ uint8_t dynq[];
    const uint32_t kb  = (smem_u32(dynq) + 1023) & ~1023u;
    const uint32_t qb0 = kb + 16384;
    const uint32_t qb1 = qb0 + 8192;
    const uint32_t pb0 = qb1 + 8192;
    const uint32_t pb1 = pb0 + 16384;

    const int tid = threadIdx.x, wid = tid >> 5, lid = tid & 31;
    const int k0 = blockIdx.x * 128;
    const int qh = blockIdx.y;           // q half: [qh*2048, qh*2048+2048)
    const int b  = blockIdx.z;

    // stage K tile (pure copy: layout already [k][hi|lo])
    {
        const uint8_t* Ks = (const uint8_t*)g_Khl + ((size_t)b * NN + k0) * 128;
        const int r = tid >> 1, seg = (tid & 1) * 64;
#pragma unroll
        for (int j = 0; j < 4; j++) {
            const uint4 d = *(const uint4*)(Ks + (size_t)r * 128 + seg + j * 16);
            STS128U(kb + SWZ((uint32_t)(r * 128 + seg + j * 16)), d.x, d.y, d.z, d.w);
        }
    }

    const uint8_t* Qs = (const uint8_t*)g_Qhl +
                        ((size_t)b * NN + (size_t)qh * (NN / 2)) * 128;
    __nv_bfloat16* Pb = g_P + (size_t)b * NN * NN;

    const int frow = lid & 15, fhc = (lid >> 4) * 16;
    const int er = lid >> 2, ec = (lid & 3) * 2;
    const int sqr = tid >> 2, sqseg = (tid & 3) * 32;
    const int cpr = tid >> 1, cpseg = (tid & 1) * 64;

    float l0 = 0.f, l1 = 0.f;

    // prefetch Q chunk 0 into regs
    uint4 qpre[2];
#pragma unroll
    for (int j = 0; j < 2; j++)
        qpre[j] = *(const uint4*)(Qs + (size_t)sqr * 128 + sqseg + j * 16);

    for (int cn = 0; cn < NN / 128; cn++) {      // 32 chunks of 64 q
        const uint32_t qb = (cn & 1) ? qb1 : qb0;
        const uint32_t pb = (cn & 1) ? pb1 : pb0;

        // store this chunk's Q from regs; prefetch next
#pragma unroll
        for (int j = 0; j < 2; j++)
            STS128U(qb + SWZ((uint32_t)(sqr * 128 + sqseg + j * 16)),
                    qpre[j].x, qpre[j].y, qpre[j].z, qpre[j].w);
        if (cn + 1 < NN / 128) {
#pragma unroll
            for (int j = 0; j < 2; j++)
                qpre[j] = *(const uint4*)(Qs + (size_t)((cn + 1) * 64 + sqr) * 128
                                          + sqseg + j * 16);
        }
        __syncthreads();   // qbuf[cn] ready; pbuf[cn-1] exp-stores complete

        // copy out previous chunk's P tile (coalesced uint4)
        if (cn > 0) {
            const uint32_t pprev = (cn & 1) ? pb0 : pb1;
            const size_t qc = (size_t)qh * (NN / 2) + (size_t)(cn - 1) * 64;
            uint8_t* dst = (uint8_t*)(Pb + (size_t)(k0 + cpr) * NN + qc) + cpseg;
#pragma unroll
            for (int j = 0; j < 4; j++) {
                uint32_t a, b2, c, d;
                LDS128U(a, b2, c, d, pprev + SWZ((uint32_t)(cpr * 128 + cpseg + j * 16)));
                *(uint4*)(dst + j * 16) = make_uint4(a, b2, c, d);
            }
        }

        float sa[8][4];
#pragma unroll
        for (int i = 0; i < 8; i++)
#pragma unroll
            for (int j = 0; j < 4; j++) sa[i][j] = 0.f;

#pragma unroll
        for (int s = 0; s < 2; s++) {
            uint32_t Ah[4], Al[4];
            LDMX4(Ah[0], Ah[1], Ah[2], Ah[3],
                  kb + SWZ((uint32_t)((wid * 16 + frow) * 128 + s * 32 + fhc)));
            LDMX4(Al[0], Al[1], Al[2], Al[3],
                  kb + SWZ((uint32_t)((wid * 16 + frow) * 128 + 64 + s * 32 + fhc)));
#pragma unroll
            for (int qg = 0; qg < 4; qg++) {
                uint32_t Bh[4], Bl[4];
                LDMX4(Bh[0], Bh[1], Bh[2], Bh[3],
                      qb + SWZ((uint32_t)((qg * 16 + frow) * 128 + s * 32 + fhc)));
                LDMX4(Bl[0], Bl[1], Bl[2], Bl[3],
                      qb + SWZ((uint32_t)((qg * 16 + frow) * 128 + 64 + s * 32 + fhc)));
                MMA16816(sa[qg*2+0], Ah[0], Ah[1], Ah[2], Ah[3], Bh[0], Bh[2]);
                MMA16816(sa[qg*2+1], Ah[0], Ah[1], Ah[2], Ah[3], Bh[1], Bh[3]);
                MMA16816(sa[qg*2+0], Ah[0], Ah[1], Ah[2], Ah[3], Bl[0], Bl[2]);
                MMA16816(sa[qg*2+1], Ah[0], Ah[1], Ah[2], Ah[3], Bl[1], Bl[3]);
                MMA16816(sa[qg*2+0], Al[0], Al[1], Al[2], Al[3], Bh[0], Bh[2]);
                MMA16816(sa[qg*2+1], Al[0], Al[1], Al[2], Al[3], Bh[1], Bh[3]);
            }
        }

        // exp, accumulate L, stage P tile into pbuf[cn&1]
#pragma unroll
        for (int n8 = 0; n8 < 8; n8++) {
            const float e0 = fexp(sa[n8][0]);
            const float e1 = fexp(sa[n8][1]);
            const float e2 = fexp(sa[n8][2]);
            const float e3 = fexp(sa[n8][3]);
            l0 += e0 + e1;
            l1 += e2 + e3;
            const int qq = n8 * 8 + ec;
            STS32U(pb + SWZ((uint32_t)((wid * 16 + er) * 128 + qq * 2)),
                   pack_bf16(e0, e1));
            STS32U(pb + SWZ((uint32_t)((wid * 16 + er + 8) * 128 + qq * 2)),
                   pack_bf16(e2, e3));
        }
    }

    __syncthreads();   // last pbuf complete
    {
        const int cn = NN / 128 - 1;
        const uint32_t plast = (cn & 1) ? pb1 : pb0;
        const size_t qc = (size_t)qh * (NN / 2) + (size_t)cn * 64;
        uint8_t* dst = (uint8_t*)(Pb + (size_t)(k0 + cpr) * NN + qc) + cpseg;
#pragma unroll
        for (int j = 0; j < 4; j++) {
            uint32_t a, b2, c, d;
            LDS128U(a, b2, c, d, plast + SWZ((uint32_t)(cpr * 128 + cpseg + j * 16)));
            *(uint4*)(dst + j * 16) = make_uint4(a, b2, c, d);
        }
    }

    // reduce L over the 4 lanes sharing a row, write partials
    l0 += __shfl_xor_sync(0xFFFFFFFF, l0, 1);
    l0 += __shfl_xor_sync(0xFFFFFFFF, l0, 2);
    l1 += __shfl_xor_sync(0xFFFFFFFF, l1, 1);
    l1 += __shfl_xor_sync(0xFFFFFFFF, l1, 2);
    if ((lid & 3) == 0) {
        g_Lpart[((size_t)b * NN + k0 + wid * 16 + er) * 2 + qh]     = l0;
        g_Lpart[((size_t)b * NN + k0 + wid * 16 + er + 8) * 2 + qh] = l1;
    }
}

// ============================================================
// OV via mma.sync: D[c,k] = sum_q V[c,q]*P[k,q]
// Double-buffered A/B tiles, 1 sync per chunk.
// Block tile: 128 c x 128 k, q-chunks 64. 8 warps = 4(m) x 2(n).
// out = x + gamma * (1/L[k]) * D
// ============================================================
__global__ void __launch_bounds__(256) ov_mma_kernel(
    const float* __restrict__ x, const float* __restrict__ gamma,
    float* __restrict__ out)
{
    extern __shared__ uint8_t dyno[];
    __shared__ float Lsh[128];

    const uint32_t ab0 = (smem_u32(dyno) + 1023) & ~1023u;
    const uint32_t ab1 = ab0 + 16384;
    const uint32_t bb0 = ab1 + 16384;
    const uint32_t bb1 = bb0 + 16384;

    const int tid = threadIdx.x;
    const int wid = tid >> 5;
    const int lid = tid & 31;
    const int wm = wid >> 1;            // 0..3 : c block of 32
    const int wn = wid & 1;             // 0..1 : k block of 64
    const int k0 = blockIdx.x * 128;
    const int c0 = blockIdx.y * 128;
    const int b  = blockIdx.z;

    if (tid < 128) {
        const float2 lp = *(const float2*)&g_Lpart[((size_t)b * NN + k0 + tid) * 2];
        Lsh[tid] = 1.f / (lp.x + lp.y);
    }

    const __nv_bfloat16* Vg = g_Vbf + ((size_t)b * CC + c0) * NN;
    const __nv_bfloat16* Pg = g_P + (size_t)b * NN * NN;

    const int srow = tid >> 1;          // 0..127
    const int qo = (tid & 1) * 32;      // element offset (half row)

    uint4 a_pre[4], b_pre[4];
#pragma unroll
    for (int j = 0; j < 4; j++) {
        a_pre[j] = *(const uint4*)&Vg[(size_t)srow * NN + qo + j * 8];
        b_pre[j] = *(const uint4*)&Pg[(size_t)(k0 + srow) * NN + qo + j * 8];
    }

    float acc[2][8][4];
#pragma unroll
    for (int mt = 0; mt < 2; mt++)
#pragma unroll
        for (int nt = 0; nt < 8; nt++)
#pragma unroll
            for (int i = 0; i < 4; i++) acc[mt][nt][i] = 0.f;

    const int frow = lid & 15;
    const int fcb  = (lid >> 4) * 16;

    for (int chunk = 0; chunk < NN / 64; chunk++) {
        const uint32_t abase = (chunk & 1) ? ab1 : ab0;
        const uint32_t bbase = (chunk & 1) ? bb1 : bb0;

        // store this chunk from regs, prefetch next chunk
#pragma unroll
        for (int j = 0; j < 4; j++) {
            STS128U(abase + SWZ((uint32_t)(srow * 128 + qo * 2 + j * 16)),
                    a_pre[j].x, a_pre[j].y, a_pre[j].z, a_pre[j].w);
            STS128U(bbase + SWZ((uint32_t)(srow * 128 + qo * 2 + j * 16)),
                    b_pre[j].x, b_pre[j].y, b_pre[j].z, b_pre[j].w);
        }
        if (chunk + 1 < NN / 64) {
            const int qc = (chunk + 1) * 64;
#pragma unroll
            for (int j = 0; j < 4; j++) {
                a_pre[j] = *(const uint4*)&Vg[(size_t)srow * NN + qc + qo + j * 8];
                b_pre[j] = *(const uint4*)&Pg[(size_t)(k0 + srow) * NN + qc + qo + j * 8];
            }
        }
        __syncthreads();   // buf[chunk] ready (and mma[chunk-2] long done)

#pragma unroll
        for (int ks = 0; ks < 4; ks++) {
            const uint32_t cib = ks * 32 + fcb;
            uint32_t Am[2][4];
#pragma unroll
            for (int mt = 0; mt < 2; mt++)
                LDMX4(Am[mt][0], Am[mt][1], Am[mt][2], Am[mt][3],
                      abase + SWZ((uint32_t)((wm * 32 + mt * 16 + frow) * 128 + cib)));
            uint32_t Bf[4][4];
#pragma unroll
            for (int g = 0; g < 4; g++)
                LDMX4(Bf[g][0], Bf[g][1], Bf[g][2], Bf[g][3],
                      bbase + SWZ((uint32_t)((wn * 64 + g * 16 + frow) * 128 + cib)));
#pragma unroll
            for (int mt = 0; mt < 2; mt++)
#pragma unroll
                for (int g = 0; g < 4; g++) {
                    MMA16816(acc[mt][2 * g],     Am[mt][0], Am[mt][1], Am[mt][2], Am[mt][3],
                             Bf[g][0], Bf[g][2]);
                    MMA16816(acc[mt][2 * g + 1], Am[mt][0], Am[mt][1], Am[mt][2], Am[mt][3],
                             Bf[g][1], Bf[g][3]);
                }
        }
    }

    // epilogue: out = x + g * Linv[k] * D
    const float g = gamma[0];
    const int er = lid >> 2;
    const int ec = (lid & 3) * 2;
#pragma unroll
    for (int mt = 0; mt < 2; mt++) {
#pragma unroll
        for (int nt = 0; nt < 8; nt++) {
            const int kk = wn * 64 + nt * 8 + ec;
            const float l0 = Lsh[kk], l1 = Lsh[kk + 1];
#pragma unroll
            for (int h = 0; h < 2; h++) {
                const int c = c0 + wm * 32 + mt * 16 + er + h * 8;
                const size_t idx = ((size_t)b * CC + c) * NN + k0 + kk;
                const float2 xv = *(const float2*)&x[idx];
                float2 o;
                o.x = xv.x + g * l0 * acc[mt][nt][h * 2 + 0];
                o.y = xv.y + g * l1 * acc[mt][nt][h * 2 + 1];
                *(float2*)&out[idx] = o;
            }
        }
    }
}

// ============================================================
extern "C" void kernel_launch(void* const* d_in, const int* in_sizes, int n_in,
                              void* d_out, int out_size)
{
    const float* x     = (const float*)d_in[0];
    const float* wq    = (const float*)d_in[1];
    const float* bq    = (const float*)d_in[2];
    const float* wk    = (const float*)d_in[3];
    const float* bk    = (const float*)d_in[4];
    const float* wv    = (const float*)d_in[5];
    const float* bv    = (const float*)d_in[6];
    const float* gamma = (const float*)d_in[7];
    float* out = (float*)d_out;

    float *Qp, *Kp;
    __nv_bfloat16 *Vbp, *xTp, *WtVp, *WtQKp;
    cudaGetSymbolAddress((void**)&Qp, g_Q);
    cudaGetSymbolAddress((void**)&Kp, g_K);
    cudaGetSymbolAddress((void**)&Vbp, g_Vbf);
    cudaGetSymbolAddress((void**)&xTp, g_xT);
    cudaGetSymbolAddress((void**)&WtVp, g_WtV);
    cudaGetSymbolAddress((void**)&WtQKp, g_WtQK);

    static cudaStream_t s2 = nullptr;
    static cudaEvent_t eRoot = nullptr, eT = nullptr, eV = nullptr;
    static int attr_set = 0;
    const int SMV  = 1024 + 33792 + 2 * 16384;   // 67584
    const int SMQK = 1024 + 33792 + 2 * 8192;    // 51200
    const int SMQM = 1024 + 16384 + 2 * 8192 + 2 * 16384;  // 66560
    const int SMOV = 1024 + 4 * 16384;           // 66560
    if (!attr_set) {
        cudaFuncSetAttribute(conv_mma_kernel<128, 0>,
                             cudaFuncAttributeMaxDynamicSharedMemorySize, SMV);
        cudaFuncSetAttribute(conv_mma_kernel<64, 1>,
                             cudaFuncAttributeMaxDynamicSharedMemorySize, SMQK);
        cudaFuncSetAttribute(qk_mma_kernel,
                             cudaFuncAttributeMaxDynamicSharedMemorySize, SMQM);
        cudaFuncSetAttribute(ov_mma_kernel,
                             cudaFuncAttributeMaxDynamicSharedMemorySize, SMOV);
        cudaStreamCreateWithFlags(&s2, cudaStreamNonBlocking);
        cudaEventCreateWithFlags(&eRoot, cudaEventDisableTiming);
        cudaEventCreateWithFlags(&eT, cudaEventDisableTiming);
        cudaEventCreateWithFlags(&eV, cudaEventDisableTiming);
        attr_set = 1;
    }

    // fork s2 from the capture stream
    cudaEventRecord(eRoot, 0);
    cudaStreamWaitEvent(s2, eRoot, 0);

    // stream 0: transpose + QK weight pack
    transpose_kernel<<<dim3(NN / 32, CC / 32, BB), dim3(32, 8)>>>(x, xTp);
    pack_wqk_kernel<<<(9 * 64 * CC) / 256, 256>>>(wq, wk, WtQKp);
    cudaEventRecord(eT, 0);

    // stream s2: V weight pack, then (after transpose) conv-V
    pack_wv_kernel<<<(9 * CC * CC) / 256, 256, 0, s2>>>(wv, WtVp);
    cudaStreamWaitEvent(s2, eT, 0);
    conv_mma_kernel<128, 0><<<dim3(32, 2, BB), 256, SMV, s2>>>(
        xTp, WtVp, bv, nullptr, Vbp, nullptr);
    cudaEventRecord(eV, s2);

    // stream 0: QK chain (runs concurrently with conv-V)
    conv_mma_kernel<64, 1><<<dim3(32, 1, BB), 256, SMQK>>>(
        xTp, WtQKp, bq, bk, Qp, Kp);
    qkpack_kernel<<<dim3(NN / 64, 2, BB), 256>>>();
    qk_mma_kernel<<<dim3(NN / 128, 2, BB), 256, SMQM>>>();

    // join and run OV
    cudaStreamWaitEvent(0, eV, 0);
    ov_mma_kernel<<<dim3(NN / 128, CC / 128, BB), 256, SMOV>>>(x, gamma, out);
}